// round 12
// baseline (speedup 1.0000x reference)
#include <cuda_runtime.h>

#define LN 1024
#define BATCH 64
#define THREADS 256
#define NCG 16
#define RPT 4
#define ROWS_PER_CTA 64
#define TILES (LN / ROWS_PER_CTA)     // 16
#define PAIRS (TILES / 2)             // 8 complementary tile-pairs
#define YDIM (PAIRS + 1)              // 8 pair slots + 1 header slot
#define TOTAL_CTAS (BATCH * YDIM)     // 576 -> single wave at occ 4

typedef unsigned long long u64;

// Scratch (device globals; no runtime allocation).
__device__ ulonglong2 g_colA[BATCH][LN];  // ( pack(x0,y0), pack(x1,y1) )
__device__ ulonglong2 g_colB[BATCH][LN];  // ( pack(x2,y2), pack(sqx, sqy_or_sentinel) )
__device__ float      g_msk[BATCH][LN];   // 1.0 if y-row observed else 0.0 (header only)
__device__ u64        g_hdr[BATCH][4];    // S0,S1,S2,SQ packed masked sums
__device__ float      g_nvf[BATCH];
__device__ float      g_part[TOTAL_CTAS];
__device__ int        g_ctr = 0;

#define SENTINEL (-1e30f)
#define SENT_CHK (-1e29f)

// ---------- f32x2 helpers ----------
__device__ __forceinline__ u64 fma2(u64 a, u64 b, u64 c) {
    u64 d; asm("fma.rn.f32x2 %0, %1, %2, %3;" : "=l"(d) : "l"(a), "l"(b), "l"(c)); return d;
}
__device__ __forceinline__ u64 add2(u64 a, u64 b) {
    u64 d; asm("add.rn.f32x2 %0, %1, %2;" : "=l"(d) : "l"(a), "l"(b)); return d;
}
__device__ __forceinline__ u64 mul2(u64 a, u64 b) {
    u64 d; asm("mul.rn.f32x2 %0, %1, %2;" : "=l"(d) : "l"(a), "l"(b)); return d;
}
__device__ __forceinline__ u64 pack2(float lo, float hi) {
    u64 d; asm("mov.b64 %0, {%1, %2};" : "=l"(d) : "f"(lo), "f"(hi)); return d;
}
__device__ __forceinline__ float2 unpack2(u64 a) {
    float lo, hi; asm("mov.b64 {%0, %1}, %2;" : "=f"(lo), "=f"(hi) : "l"(a));
    return make_float2(lo, hi);
}
__device__ __forceinline__ float fast_sqrt(float a) {
    float r; asm("sqrt.approx.f32 %0, %1;" : "=f"(r) : "f"(a)); return r;
}

#define NEG2_PACKED 0xC0000000C0000000ULL  // (-2.0f, -2.0f)

// ---------- pre-kernel: transform + sentinel, coalesced, 2 residues/thread ----------
__global__ __launch_bounds__(THREADS)
void pre_kernel(const float* __restrict__ x, const float* __restrict__ y) {
    const int tid = threadIdx.x;
    const int b  = tid & (BATCH - 1);
    const int dl = tid >> 6;                 // 0..3
    const int l0 = blockIdx.x * 8 + dl * 2;  // grid = LN/8 = 128

#pragma unroll
    for (int i = 0; i < 2; i++) {
        const int l = l0 + i;
        const int base = (l * BATCH + b) * 3;
        float x0 = x[base], x1 = x[base + 1], x2 = x[base + 2];
        float y0 = y[base], y1 = y[base + 1], y2 = y[base + 2];
        float sqx = fmaf(x2, x2, fmaf(x1, x1, x0 * x0));
        float sqy = fmaf(y2, y2, fmaf(y1, y1, y0 * y0));
        bool valid = ((y0 + y1 + y2) != 0.0f);

        ulonglong2 qa, qb;
        qa.x = pack2(x0, y0); qa.y = pack2(x1, y1);
        qb.x = pack2(x2, y2);
        qb.y = pack2(sqx, valid ? sqy : SENTINEL);  // sentinel folds the mask
        g_colA[b][l] = qa;
        g_colB[b][l] = qb;
        g_msk[b][l]  = valid ? 1.0f : 0.0f;
    }
}

// One triangular row-tile: diag block (weight 1) + strict upper columns (weight 2).
// Returns this thread's cross-term contribution (already * -2).
__device__ __forceinline__ float do_tile(const ulonglong2* __restrict__ sA,
                                         const ulonglong2* __restrict__ sB,
                                         int R, int cg, int rg) {
    const int row0 = R + rg * RPT;

    u64 a0[RPT], a1[RPT], a2[RPT], cr[RPT];
    float accD[RPT] = {0, 0, 0, 0};
    float accU[RPT] = {0, 0, 0, 0};
    float rowmax = SENTINEL;
#pragma unroll
    for (int r = 0; r < RPT; r++) {
        ulonglong2 qA = sA[row0 + r];
        ulonglong2 qB = sB[row0 + r];
        a0[r] = mul2(qA.x, NEG2_PACKED);
        a1[r] = mul2(qA.y, NEG2_PACKED);
        a2[r] = mul2(qB.x, NEG2_PACKED);
        cr[r] = qB.y;
        rowmax = fmaxf(rowmax, unpack2(qB.y).y);  // sqy or SENTINEL
    }

    if (rowmax > SENT_CHK) {
        // diagonal 64-col tile: full square block (both orders), weight 1
#pragma unroll
        for (int j = 0; j < 4; j++) {
            int k = R + j * NCG + cg;
            ulonglong2 qA = sA[k];
            ulonglong2 qB = sB[k];
#pragma unroll
            for (int r = 0; r < RPT; r++) {
                u64 t = fma2(a0[r], qA.x, cr[r]);
                t = fma2(a1[r], qA.y, t);
                t = fma2(a2[r], qB.x, t);
                t = add2(t, qB.y);
                float2 d = unpack2(t);               // (d2x, d2y)
                float prod = fmaxf(d.x, 0.0f) * d.y; // clamp d2x first: sentinel safe
                accD[r] += fast_sqrt(fmaxf(prod, 0.0f));
            }
        }
        // strict upper columns: counted twice by symmetry
#pragma unroll 4
        for (int k = R + ROWS_PER_CTA + cg; k < LN; k += NCG) {
            ulonglong2 qA = sA[k];
            ulonglong2 qB = sB[k];
#pragma unroll
            for (int r = 0; r < RPT; r++) {
                u64 t = fma2(a0[r], qA.x, cr[r]);
                t = fma2(a1[r], qA.y, t);
                t = fma2(a2[r], qB.x, t);
                t = add2(t, qB.y);
                float2 d = unpack2(t);
                float prod = fmaxf(d.x, 0.0f) * d.y;
                accU[r] += fast_sqrt(fmaxf(prod, 0.0f));
            }
        }
    }

    float c = 0.0f;
#pragma unroll
    for (int r = 0; r < RPT; r++)
        c -= 2.0f * fmaf(2.0f, accU[r], accD[r]);
    return c;
}

// ---------- pair kernel: complementary tile pairs (t, 15-t) => uniform work ----------
__global__ __launch_bounds__(THREADS, 4)
void pair_kernel(float* __restrict__ out) {
    const int b = blockIdx.x, slot = blockIdx.y, tid = threadIdx.x;
    const int warp = tid >> 5, lane = tid & 31;

    __shared__ ulonglong2 sA[LN];
    __shared__ ulonglong2 sB[LN];
    __shared__ float s_red[8][9];
    __shared__ float wsum[8];
    __shared__ int   s_last;

    float tsum = 0.0f;

    if (slot == PAIRS) {
        // ===== header CTA: per-batch masked sums from global (deterministic) =====
        float s[9] = {0, 0, 0, 0, 0, 0, 0, 0, 0};
#pragma unroll
        for (int i = tid; i < LN; i += THREADS) {
            ulonglong2 qa = g_colA[b][i];
            ulonglong2 qb = g_colB[b][i];
            float m = g_msk[b][i];
            float2 p0 = unpack2(qa.x), p1 = unpack2(qa.y);
            float2 p2 = unpack2(qb.x), pq = unpack2(qb.y);
            s[0] = fmaf(m, p0.x, s[0]); s[1] = fmaf(m, p0.y, s[1]);
            s[2] = fmaf(m, p1.x, s[2]); s[3] = fmaf(m, p1.y, s[3]);
            s[4] = fmaf(m, p2.x, s[4]); s[5] = fmaf(m, pq.x, s[5]);
            s[6] = fmaf(m, p2.y, s[6]); s[7] = fmaf(m, pq.y, s[7]);
            s[8] += m;
        }
#pragma unroll
        for (int k = 0; k < 9; k++)
#pragma unroll
            for (int o = 16; o > 0; o >>= 1)
                s[k] += __shfl_down_sync(0xffffffffu, s[k], o);
        if (lane == 0)
#pragma unroll
            for (int k = 0; k < 9; k++) s_red[warp][k] = s[k];
        __syncthreads();
        if (tid == 0) {
            float t[9] = {0, 0, 0, 0, 0, 0, 0, 0, 0};
            for (int w = 0; w < 8; w++)
                for (int k = 0; k < 9; k++) t[k] += s_red[w][k];
            g_hdr[b][0] = pack2(t[0], t[1]);   // (Sx0, Sy0)
            g_hdr[b][1] = pack2(t[2], t[3]);   // (Sx1, Sy1)
            g_hdr[b][2] = pack2(t[4], t[6]);   // (Sx2, Sy2)
            g_hdr[b][3] = pack2(t[5], t[7]);   // (SQx, SQy)
            g_nvf[b] = t[8];
        }
    } else {
        // ===== pair CTA: tiles (slot, TILES-1-slot); fill covers both =====
        const int t_lo = slot;                  // 0..7
        const int t_hi = TILES - 1 - slot;      // 15..8
        const int fill0 = t_lo * ROWS_PER_CTA;  // lower tile starts earlier

        for (int i = fill0 + tid; i < LN; i += THREADS) {
            sA[i] = g_colA[b][i];
            sB[i] = g_colB[b][i];
        }
        __syncthreads();

        const int cg = tid & (NCG - 1);
        const int rg = tid >> 4;

        tsum  = do_tile(sA, sB, t_lo * ROWS_PER_CTA, cg, rg);   // 64-4*slot steps
        tsum += do_tile(sA, sB, t_hi * ROWS_PER_CTA, cg, rg);   // 4+4*slot steps
    }

    // ---- deterministic block reduce ----
#pragma unroll
    for (int o = 16; o > 0; o >>= 1)
        tsum += __shfl_down_sync(0xffffffffu, tsum, o);
    if ((tid & 31) == 0) wsum[tid >> 5] = tsum;
    __syncthreads();
    if (tid == 0) {
        float v = 0.0f;
        for (int w = 0; w < 8; w++) v += wsum[w];
        g_part[b * YDIM + slot] = v;
        __threadfence();   // orders g_part AND g_hdr before the counter arrive
        int old = atomicAdd(&g_ctr, 1);
        s_last = (old == TOTAL_CTAS - 1) ? 1 : 0;
    }
    __syncthreads();

    // ---- last CTA: fused final reduction (deterministic fixed-order reads) ----
    if (s_last) {
        float v = 0.0f;
        if (tid < BATCH) {
            // header term: 2 * (nv*(SQx+SQy) - |Sx|^2 - |Sy|^2)
            float2 S0 = unpack2(__ldcg((u64*)&g_hdr[tid][0]));
            float2 S1 = unpack2(__ldcg((u64*)&g_hdr[tid][1]));
            float2 S2 = unpack2(__ldcg((u64*)&g_hdr[tid][2]));
            float2 SQ = unpack2(__ldcg((u64*)&g_hdr[tid][3]));
            float nv = __ldcg(&g_nvf[tid]);
            float s2 = S0.x * S0.x + S1.x * S1.x + S2.x * S2.x
                     + S0.y * S0.y + S1.y * S1.y + S2.y * S2.y;
            float F = 2.0f * (nv * (SQ.x + SQ.y) - s2);
            for (int t = 0; t < YDIM; t++)
                F += __ldcg(&g_part[tid * YDIM + t]);
            v = fast_sqrt(fmaxf(F, 0.0f));
        }
#pragma unroll
        for (int o = 16; o > 0; o >>= 1)
            v += __shfl_down_sync(0xffffffffu, v, o);
        if ((tid & 31) == 0) wsum[tid >> 5] = v;
        __syncthreads();
        if (tid == 0) {
            const float denom = 723.3699523f;  // sqrt(1024^2/2 - 1024)
            out[0] = (wsum[0] + wsum[1]) / denom / (float)BATCH;
            g_ctr = 0;                          // reset for next graph replay
        }
    }
}

extern "C" void kernel_launch(void* const* d_in, const int* in_sizes, int n_in,
                              void* d_out, int out_size) {
    const float* x = (const float*)d_in[0];
    const float* y = (const float*)d_in[1];
    float* out = (float*)d_out;
    (void)in_sizes; (void)n_in; (void)out_size;

    pre_kernel<<<LN / 8, THREADS>>>(x, y);
    dim3 grid(BATCH, YDIM);   // 576 CTAs: single wave at 4 CTAs/SM, uniform work
    pair_kernel<<<grid, THREADS>>>(out);
}

// round 13
// speedup vs baseline: 1.1495x; 1.1495x over previous
#include <cuda_runtime.h>

#define LN 1024
#define BATCH 64
#define THREADS 256
#define NCG 16
#define RPT 4
#define ROWS_PER_CTA 64
#define TILES (LN / ROWS_PER_CTA)
#define YDIM (TILES + 1)            // 16 pair tiles + 1 header tile
#define TOTAL_CTAS (BATCH * YDIM)

typedef unsigned long long u64;

// Scratch (device globals; no runtime allocation).
__device__ ulonglong2 g_colA[BATCH][LN];  // ( pack(x0,y0), pack(x1,y1) )
__device__ ulonglong2 g_colB[BATCH][LN];  // ( pack(x2,y2), pack(sqx, sqy_or_sentinel) )
__device__ float      g_msk[BATCH][LN];   // 1.0 if y-row observed else 0.0 (header only)
__device__ u64        g_hdr[BATCH][4];    // S0,S1,S2,SQ packed masked sums
__device__ float      g_nvf[BATCH];
__device__ float      g_part[TOTAL_CTAS];
__device__ int        g_ctr = 0;

#define SENTINEL (-1e30f)
#define SENT_CHK (-1e29f)

// ---------- f32x2 helpers ----------
__device__ __forceinline__ u64 fma2(u64 a, u64 b, u64 c) {
    u64 d; asm("fma.rn.f32x2 %0, %1, %2, %3;" : "=l"(d) : "l"(a), "l"(b), "l"(c)); return d;
}
__device__ __forceinline__ u64 add2(u64 a, u64 b) {
    u64 d; asm("add.rn.f32x2 %0, %1, %2;" : "=l"(d) : "l"(a), "l"(b)); return d;
}
__device__ __forceinline__ u64 mul2(u64 a, u64 b) {
    u64 d; asm("mul.rn.f32x2 %0, %1, %2;" : "=l"(d) : "l"(a), "l"(b)); return d;
}
__device__ __forceinline__ u64 pack2(float lo, float hi) {
    u64 d; asm("mov.b64 %0, {%1, %2};" : "=l"(d) : "f"(lo), "f"(hi)); return d;
}
__device__ __forceinline__ float2 unpack2(u64 a) {
    float lo, hi; asm("mov.b64 {%0, %1}, %2;" : "=f"(lo), "=f"(hi) : "l"(a));
    return make_float2(lo, hi);
}
__device__ __forceinline__ float fast_sqrt(float a) {
    float r; asm("sqrt.approx.f32 %0, %1;" : "=f"(r) : "f"(a)); return r;
}

#define NEG2_PACKED 0xC0000000C0000000ULL  // (-2.0f, -2.0f)

// ---------- pre-kernel: transform + sentinel, coalesced, 2 residues/thread ----------
__global__ __launch_bounds__(THREADS)
void pre_kernel(const float* __restrict__ x, const float* __restrict__ y) {
    const int tid = threadIdx.x;
    const int b  = tid & (BATCH - 1);
    const int dl = tid >> 6;                 // 0..3
    const int l0 = blockIdx.x * 8 + dl * 2;  // grid = LN/8 = 128

#pragma unroll
    for (int i = 0; i < 2; i++) {
        const int l = l0 + i;
        const int base = (l * BATCH + b) * 3;
        float x0 = x[base], x1 = x[base + 1], x2 = x[base + 2];
        float y0 = y[base], y1 = y[base + 1], y2 = y[base + 2];
        float sqx = fmaf(x2, x2, fmaf(x1, x1, x0 * x0));
        float sqy = fmaf(y2, y2, fmaf(y1, y1, y0 * y0));
        bool valid = ((y0 + y1 + y2) != 0.0f);

        ulonglong2 qa, qb;
        qa.x = pack2(x0, y0); qa.y = pack2(x1, y1);
        qb.x = pack2(x2, y2);
        qb.y = pack2(sqx, valid ? sqy : SENTINEL);  // sentinel folds the mask
        g_colA[b][l] = qa;
        g_colB[b][l] = qb;
        g_msk[b][l]  = valid ? 1.0f : 0.0f;
    }
}

// ---------- pair kernel: triangular cross term; tile==TILES CTAs do headers ----------
__global__ __launch_bounds__(THREADS, 4)
void pair_kernel(float* __restrict__ out) {
    const int b = blockIdx.x, tile = blockIdx.y, tid = threadIdx.x;
    const int warp = tid >> 5, lane = tid & 31;

    __shared__ ulonglong2 sA[LN];
    __shared__ ulonglong2 sB[LN];
    __shared__ float s_red[8][9];
    __shared__ int   s_kred[8];
    __shared__ float wsum[8];
    __shared__ int   s_last;

    float tsum = 0.0f;

    if (tile == TILES) {
        // ===== header CTA: per-batch masked sums from global (deterministic) =====
        float s[9] = {0, 0, 0, 0, 0, 0, 0, 0, 0};
#pragma unroll
        for (int i = tid; i < LN; i += THREADS) {
            ulonglong2 qa = g_colA[b][i];
            ulonglong2 qb = g_colB[b][i];
            float m = g_msk[b][i];
            float2 p0 = unpack2(qa.x), p1 = unpack2(qa.y);
            float2 p2 = unpack2(qb.x), pq = unpack2(qb.y);
            s[0] = fmaf(m, p0.x, s[0]); s[1] = fmaf(m, p0.y, s[1]);
            s[2] = fmaf(m, p1.x, s[2]); s[3] = fmaf(m, p1.y, s[3]);
            s[4] = fmaf(m, p2.x, s[4]); s[5] = fmaf(m, pq.x, s[5]);
            s[6] = fmaf(m, p2.y, s[6]); s[7] = fmaf(m, pq.y, s[7]);
            s[8] += m;
        }
#pragma unroll
        for (int k = 0; k < 9; k++)
#pragma unroll
            for (int o = 16; o > 0; o >>= 1)
                s[k] += __shfl_down_sync(0xffffffffu, s[k], o);
        if (lane == 0)
#pragma unroll
            for (int k = 0; k < 9; k++) s_red[warp][k] = s[k];
        __syncthreads();
        if (tid == 0) {
            float t[9] = {0, 0, 0, 0, 0, 0, 0, 0, 0};
            for (int w = 0; w < 8; w++)
                for (int k = 0; k < 9; k++) t[k] += s_red[w][k];
            g_hdr[b][0] = pack2(t[0], t[1]);   // (Sx0, Sy0)
            g_hdr[b][1] = pack2(t[2], t[3]);   // (Sx1, Sy1)
            g_hdr[b][2] = pack2(t[4], t[6]);   // (Sx2, Sy2)
            g_hdr[b][3] = pack2(t[5], t[7]);   // (SQx, SQy)
            g_nvf[b] = t[8];
        }
        // tsum stays 0
    } else {
        // ===== pair CTA =====
        const int R = tile * ROWS_PER_CTA;

        // fill columns [R, LN); track max valid column index (+1) seen
        int lmax = 0;
        for (int i = R + tid; i < LN; i += THREADS) {
            ulonglong2 qa = g_colA[b][i];
            ulonglong2 qb = g_colB[b][i];
            sA[i] = qa;
            sB[i] = qb;
            if (unpack2(qb.y).y > SENT_CHK) lmax = i + 1;  // loop ascends: last wins
        }
#pragma unroll
        for (int o = 16; o > 0; o >>= 1)
            lmax = max(lmax, __shfl_down_sync(0xffffffffu, lmax, o));
        if (lane == 0) s_kred[warp] = lmax;
        __syncthreads();

        int kmax = s_kred[0];
#pragma unroll
        for (int w = 1; w < 8; w++) kmax = max(kmax, s_kred[w]);

        const int cg = tid & (NCG - 1);
        const int rg = tid >> 4;
        const int row0 = R + rg * RPT;

        u64 a0[RPT], a1[RPT], a2[RPT], cr[RPT];
        float accD[RPT] = {0, 0, 0, 0};   // diagonal tile, weight 1
        float accU[RPT] = {0, 0, 0, 0};   // strict upper tiles, weight 2
        float rowmax = SENTINEL;
#pragma unroll
        for (int r = 0; r < RPT; r++) {
            ulonglong2 qA = sA[row0 + r];
            ulonglong2 qB = sB[row0 + r];
            a0[r] = mul2(qA.x, NEG2_PACKED);
            a1[r] = mul2(qA.y, NEG2_PACKED);
            a2[r] = mul2(qB.x, NEG2_PACKED);
            cr[r] = qB.y;
            rowmax = fmaxf(rowmax, unpack2(qB.y).y);  // sqy or SENTINEL
        }

        if (rowmax > SENT_CHK) {   // at least one valid row in this quad
            // diagonal 64-col tile: full square block (both orders), weight 1
#pragma unroll
            for (int j = 0; j < 4; j++) {
                int k = R + j * NCG + cg;
                ulonglong2 qA = sA[k];
                ulonglong2 qB = sB[k];
#pragma unroll
                for (int r = 0; r < RPT; r++) {
                    u64 t = fma2(a0[r], qA.x, cr[r]);
                    t = fma2(a1[r], qA.y, t);
                    t = fma2(a2[r], qB.x, t);
                    t = add2(t, qB.y);
                    float2 d = unpack2(t);               // (d2x, d2y)
                    // clamp d2x first so invalid (d2y=-1e30) can never flip sign
                    float prod = fmaxf(d.x, 0.0f) * d.y;
                    accD[r] += fast_sqrt(fmaxf(prod, 0.0f));
                }
            }
            // strict upper columns up to kmax (cols >= kmax are all-invalid: exact 0)
#pragma unroll 4
            for (int k = R + ROWS_PER_CTA + cg; k < kmax; k += NCG) {
                ulonglong2 qA = sA[k];
                ulonglong2 qB = sB[k];
#pragma unroll
                for (int r = 0; r < RPT; r++) {
                    u64 t = fma2(a0[r], qA.x, cr[r]);
                    t = fma2(a1[r], qA.y, t);
                    t = fma2(a2[r], qB.x, t);
                    t = add2(t, qB.y);
                    float2 d = unpack2(t);
                    float prod = fmaxf(d.x, 0.0f) * d.y;
                    accU[r] += fast_sqrt(fmaxf(prod, 0.0f));
                }
            }
        }

        // cross-term: -2 * sum_rows (accD + 2*accU); invalid pairs already 0
#pragma unroll
        for (int r = 0; r < RPT; r++)
            tsum -= 2.0f * fmaf(2.0f, accU[r], accD[r]);
    }

    // ---- deterministic block reduce ----
#pragma unroll
    for (int o = 16; o > 0; o >>= 1)
        tsum += __shfl_down_sync(0xffffffffu, tsum, o);
    if ((tid & 31) == 0) wsum[tid >> 5] = tsum;
    __syncthreads();
    if (tid == 0) {
        float v = 0.0f;
        for (int w = 0; w < 8; w++) v += wsum[w];
        g_part[b * YDIM + tile] = v;
        __threadfence();   // orders g_part AND g_hdr before the counter arrive
        int old = atomicAdd(&g_ctr, 1);
        s_last = (old == TOTAL_CTAS - 1) ? 1 : 0;
    }
    __syncthreads();

    // ---- last CTA: fused final reduction (deterministic fixed-order reads) ----
    if (s_last) {
        float v = 0.0f;
        if (tid < BATCH) {
            // header term: 2 * (nv*(SQx+SQy) - |Sx|^2 - |Sy|^2)
            float2 S0 = unpack2(__ldcg((u64*)&g_hdr[tid][0]));
            float2 S1 = unpack2(__ldcg((u64*)&g_hdr[tid][1]));
            float2 S2 = unpack2(__ldcg((u64*)&g_hdr[tid][2]));
            float2 SQ = unpack2(__ldcg((u64*)&g_hdr[tid][3]));
            float nv = __ldcg(&g_nvf[tid]);
            float s2 = S0.x * S0.x + S1.x * S1.x + S2.x * S2.x
                     + S0.y * S0.y + S1.y * S1.y + S2.y * S2.y;
            float F = 2.0f * (nv * (SQ.x + SQ.y) - s2);
            for (int t = 0; t < YDIM; t++)
                F += __ldcg(&g_part[tid * YDIM + t]);
            v = fast_sqrt(fmaxf(F, 0.0f));
        }
#pragma unroll
        for (int o = 16; o > 0; o >>= 1)
            v += __shfl_down_sync(0xffffffffu, v, o);
        if ((tid & 31) == 0) wsum[tid >> 5] = v;
        __syncthreads();
        if (tid == 0) {
            const float denom = 723.3699523f;  // sqrt(1024^2/2 - 1024)
            out[0] = (wsum[0] + wsum[1]) / denom / (float)BATCH;
            g_ctr = 0;                          // reset for next graph replay
        }
    }
}

extern "C" void kernel_launch(void* const* d_in, const int* in_sizes, int n_in,
                              void* d_out, int out_size) {
    const float* x = (const float*)d_in[0];
    const float* y = (const float*)d_in[1];
    float* out = (float*)d_out;
    (void)in_sizes; (void)n_in; (void)out_size;

    pre_kernel<<<LN / 8, THREADS>>>(x, y);
    dim3 grid(BATCH, YDIM);   // tile 0 (heaviest) launches first; header CTAs last
    pair_kernel<<<grid, THREADS>>>(out);
}

// round 15
// speedup vs baseline: 1.1617x; 1.0106x over previous
#include <cuda_runtime.h>

#define LN 1024
#define BATCH 64
#define THREADS 256
#define NCG 16
#define RPT 4
#define ROWS_PER_CTA 64
#define TILES (LN / ROWS_PER_CTA)
#define YDIM (TILES + 1)            // 16 pair tiles + 1 header tile
#define TOTAL_CTAS (BATCH * YDIM)

typedef unsigned long long u64;

// Scratch (device globals; no runtime allocation).
__device__ ulonglong2 g_colA[BATCH][LN];  // ( pack(x0,y0), pack(x1,y1) )
__device__ ulonglong2 g_colB[BATCH][LN];  // ( pack(x2,y2), pack(sqx, sqy_or_sentinel) )
__device__ float      g_msk[BATCH][LN];   // 1.0 if y-row observed else 0.0 (header only)
__device__ u64        g_hdr[BATCH][4];    // S0,S1,S2,SQ packed masked sums
__device__ float      g_nvf[BATCH];
__device__ float      g_part[TOTAL_CTAS];
__device__ int        g_ctr = 0;

#define SENTINEL (-1e30f)
#define SENT_CHK (-1e29f)

// ---------- f32x2 helpers ----------
__device__ __forceinline__ u64 fma2(u64 a, u64 b, u64 c) {
    u64 d; asm("fma.rn.f32x2 %0, %1, %2, %3;" : "=l"(d) : "l"(a), "l"(b), "l"(c)); return d;
}
__device__ __forceinline__ u64 add2(u64 a, u64 b) {
    u64 d; asm("add.rn.f32x2 %0, %1, %2;" : "=l"(d) : "l"(a), "l"(b)); return d;
}
__device__ __forceinline__ u64 mul2(u64 a, u64 b) {
    u64 d; asm("mul.rn.f32x2 %0, %1, %2;" : "=l"(d) : "l"(a), "l"(b)); return d;
}
__device__ __forceinline__ u64 pack2(float lo, float hi) {
    u64 d; asm("mov.b64 %0, {%1, %2};" : "=l"(d) : "f"(lo), "f"(hi)); return d;
}
__device__ __forceinline__ float2 unpack2(u64 a) {
    float lo, hi; asm("mov.b64 {%0, %1}, %2;" : "=f"(lo), "=f"(hi) : "l"(a));
    return make_float2(lo, hi);
}
__device__ __forceinline__ float fast_sqrt(float a) {
    float r; asm("sqrt.approx.f32 %0, %1;" : "=f"(r) : "f"(a)); return r;
}

#define NEG2_PACKED 0xC0000000C0000000ULL  // (-2.0f, -2.0f)

// ---------- pre-kernel: transform + sentinel, coalesced, 2 residues/thread ----------
__global__ __launch_bounds__(THREADS)
void pre_kernel(const float* __restrict__ x, const float* __restrict__ y) {
    const int tid = threadIdx.x;
    const int b  = tid & (BATCH - 1);
    const int dl = tid >> 6;                 // 0..3
    const int l0 = blockIdx.x * 8 + dl * 2;  // grid = LN/8 = 128

#pragma unroll
    for (int i = 0; i < 2; i++) {
        const int l = l0 + i;
        const int base = (l * BATCH + b) * 3;
        float x0 = x[base], x1 = x[base + 1], x2 = x[base + 2];
        float y0 = y[base], y1 = y[base + 1], y2 = y[base + 2];
        float sqx = fmaf(x2, x2, fmaf(x1, x1, x0 * x0));
        float sqy = fmaf(y2, y2, fmaf(y1, y1, y0 * y0));
        bool valid = ((y0 + y1 + y2) != 0.0f);

        ulonglong2 qa, qb;
        qa.x = pack2(x0, y0); qa.y = pack2(x1, y1);
        qb.x = pack2(x2, y2);
        qb.y = pack2(sqx, valid ? sqy : SENTINEL);  // sentinel folds the mask
        g_colA[b][l] = qa;
        g_colB[b][l] = qb;
        g_msk[b][l]  = valid ? 1.0f : 0.0f;
    }
}

// ---------- pair kernel: triangular cross term; tile==TILES CTAs do headers ----------
__global__ __launch_bounds__(THREADS, 4)
void pair_kernel(float* __restrict__ out) {
    const int b = blockIdx.x, tile = blockIdx.y, tid = threadIdx.x;
    const int warp = tid >> 5, lane = tid & 31;

    __shared__ ulonglong2 sA[LN];
    __shared__ ulonglong2 sB[LN];
    __shared__ float s_red[8][9];
    __shared__ int   s_kred[8];
    __shared__ float wsum[8];
    __shared__ int   s_last;

    float tsum = 0.0f;

    if (tile == TILES) {
        // ===== header CTA: per-batch masked sums from global (deterministic) =====
        float s[9] = {0, 0, 0, 0, 0, 0, 0, 0, 0};
#pragma unroll
        for (int i = tid; i < LN; i += THREADS) {
            ulonglong2 qa = g_colA[b][i];
            ulonglong2 qb = g_colB[b][i];
            float m = g_msk[b][i];
            float2 p0 = unpack2(qa.x), p1 = unpack2(qa.y);
            float2 p2 = unpack2(qb.x), pq = unpack2(qb.y);
            s[0] = fmaf(m, p0.x, s[0]); s[1] = fmaf(m, p0.y, s[1]);
            s[2] = fmaf(m, p1.x, s[2]); s[3] = fmaf(m, p1.y, s[3]);
            s[4] = fmaf(m, p2.x, s[4]); s[5] = fmaf(m, pq.x, s[5]);
            s[6] = fmaf(m, p2.y, s[6]); s[7] = fmaf(m, pq.y, s[7]);
            s[8] += m;
        }
#pragma unroll
        for (int k = 0; k < 9; k++)
#pragma unroll
            for (int o = 16; o > 0; o >>= 1)
                s[k] += __shfl_down_sync(0xffffffffu, s[k], o);
        if (lane == 0)
#pragma unroll
            for (int k = 0; k < 9; k++) s_red[warp][k] = s[k];
        __syncthreads();
        if (tid == 0) {
            float t[9] = {0, 0, 0, 0, 0, 0, 0, 0, 0};
            for (int w = 0; w < 8; w++)
                for (int k = 0; k < 9; k++) t[k] += s_red[w][k];
            g_hdr[b][0] = pack2(t[0], t[1]);   // (Sx0, Sy0)
            g_hdr[b][1] = pack2(t[2], t[3]);   // (Sx1, Sy1)
            g_hdr[b][2] = pack2(t[4], t[6]);   // (Sx2, Sy2)
            g_hdr[b][3] = pack2(t[5], t[7]);   // (SQx, SQy)
            g_nvf[b] = t[8];
        }
        // tsum stays 0
    } else {
        // ===== pair CTA =====
        const int R = tile * ROWS_PER_CTA;

        // fill columns [R, LN); track max valid column index (+1) seen
        int lmax = 0;
        for (int i = R + tid; i < LN; i += THREADS) {
            ulonglong2 qa = g_colA[b][i];
            ulonglong2 qb = g_colB[b][i];
            sA[i] = qa;
            sB[i] = qb;
            if (unpack2(qb.y).y > SENT_CHK) lmax = i + 1;  // loop ascends: last wins
        }
#pragma unroll
        for (int o = 16; o > 0; o >>= 1)
            lmax = max(lmax, __shfl_down_sync(0xffffffffu, lmax, o));
        if (lane == 0) s_kred[warp] = lmax;
        __syncthreads();

        int kmax = s_kred[0];
#pragma unroll
        for (int w = 1; w < 8; w++) kmax = max(kmax, s_kred[w]);

        const int cg = tid & (NCG - 1);
        const int rg = tid >> 4;
        const int row0 = R + rg * RPT;

        u64 a0[RPT], a1[RPT], a2[RPT], cr[RPT];
        float accD[RPT] = {0, 0, 0, 0};   // diagonal tile, weight 1
        float accU[RPT] = {0, 0, 0, 0};   // strict upper tiles, weight 2
        float rowmax = SENTINEL;
#pragma unroll
        for (int r = 0; r < RPT; r++) {
            ulonglong2 qA = sA[row0 + r];
            ulonglong2 qB = sB[row0 + r];
            a0[r] = mul2(qA.x, NEG2_PACKED);
            a1[r] = mul2(qA.y, NEG2_PACKED);
            a2[r] = mul2(qB.x, NEG2_PACKED);
            cr[r] = qB.y;
            rowmax = fmaxf(rowmax, unpack2(qB.y).y);  // sqy or SENTINEL
        }

        if (rowmax > SENT_CHK) {   // at least one valid row in this quad
            // diagonal 64-col tile: full square block (both orders), weight 1
#pragma unroll
            for (int j = 0; j < 4; j++) {
                int k = R + j * NCG + cg;
                ulonglong2 qA = sA[k];
                ulonglong2 qB = sB[k];
#pragma unroll
                for (int r = 0; r < RPT; r++) {
                    u64 t = fma2(a0[r], qA.x, cr[r]);
                    t = fma2(a1[r], qA.y, t);
                    t = fma2(a2[r], qB.x, t);
                    t = add2(t, qB.y);
                    float2 d = unpack2(t);            // (d2x, d2y)
                    // independent relu on both components: two parallel FMNMX,
                    // sentinel (d2y=-1e30) -> 0; product >= 0 by construction
                    float ex = fmaxf(d.x, 0.0f);
                    float ey = fmaxf(d.y, 0.0f);
                    accD[r] += fast_sqrt(ex * ey);
                }
            }
            // strict upper columns up to kmax (cols >= kmax are all-invalid: exact 0)
#pragma unroll 4
            for (int k = R + ROWS_PER_CTA + cg; k < kmax; k += NCG) {
                ulonglong2 qA = sA[k];
                ulonglong2 qB = sB[k];
#pragma unroll
                for (int r = 0; r < RPT; r++) {
                    u64 t = fma2(a0[r], qA.x, cr[r]);
                    t = fma2(a1[r], qA.y, t);
                    t = fma2(a2[r], qB.x, t);
                    t = add2(t, qB.y);
                    float2 d = unpack2(t);
                    float ex = fmaxf(d.x, 0.0f);
                    float ey = fmaxf(d.y, 0.0f);
                    accU[r] += fast_sqrt(ex * ey);
                }
            }
        }

        // cross-term: -2 * sum_rows (accD + 2*accU); invalid pairs already 0
#pragma unroll
        for (int r = 0; r < RPT; r++)
            tsum -= 2.0f * fmaf(2.0f, accU[r], accD[r]);
    }

    // ---- deterministic block reduce ----
#pragma unroll
    for (int o = 16; o > 0; o >>= 1)
        tsum += __shfl_down_sync(0xffffffffu, tsum, o);
    if ((tid & 31) == 0) wsum[tid >> 5] = tsum;
    __syncthreads();
    if (tid == 0) {
        float v = 0.0f;
        for (int w = 0; w < 8; w++) v += wsum[w];
        g_part[b * YDIM + tile] = v;
        __threadfence();   // orders g_part AND g_hdr before the counter arrive
        int old = atomicAdd(&g_ctr, 1);
        s_last = (old == TOTAL_CTAS - 1) ? 1 : 0;
    }
    __syncthreads();

    // ---- last CTA: fused final reduction (deterministic fixed-order reads) ----
    if (s_last) {
        float v = 0.0f;
        if (tid < BATCH) {
            // header term: 2 * (nv*(SQx+SQy) - |Sx|^2 - |Sy|^2)
            float2 S0 = unpack2(__ldcg((u64*)&g_hdr[tid][0]));
            float2 S1 = unpack2(__ldcg((u64*)&g_hdr[tid][1]));
            float2 S2 = unpack2(__ldcg((u64*)&g_hdr[tid][2]));
            float2 SQ = unpack2(__ldcg((u64*)&g_hdr[tid][3]));
            float nv = __ldcg(&g_nvf[tid]);
            float s2 = S0.x * S0.x + S1.x * S1.x + S2.x * S2.x
                     + S0.y * S0.y + S1.y * S1.y + S2.y * S2.y;
            float F = 2.0f * (nv * (SQ.x + SQ.y) - s2);
            for (int t = 0; t < YDIM; t++)
                F += __ldcg(&g_part[tid * YDIM + t]);
            v = fast_sqrt(fmaxf(F, 0.0f));
        }
#pragma unroll
        for (int o = 16; o > 0; o >>= 1)
            v += __shfl_down_sync(0xffffffffu, v, o);
        if ((tid & 31) == 0) wsum[tid >> 5] = v;
        __syncthreads();
        if (tid == 0) {
            const float denom = 723.3699523f;  // sqrt(1024^2/2 - 1024)
            out[0] = (wsum[0] + wsum[1]) / denom / (float)BATCH;
            g_ctr = 0;                          // reset for next graph replay
        }
    }
}

extern "C" void kernel_launch(void* const* d_in, const int* in_sizes, int n_in,
                              void* d_out, int out_size) {
    const float* x = (const float*)d_in[0];
    const float* y = (const float*)d_in[1];
    float* out = (float*)d_out;
    (void)in_sizes; (void)n_in; (void)out_size;

    pre_kernel<<<LN / 8, THREADS>>>(x, y);
    dim3 grid(BATCH, YDIM);   // tile 0 (heaviest) launches first; header CTAs last
    pair_kernel<<<grid, THREADS>>>(out);
}